// round 10
// baseline (speedup 1.0000x reference)
#include <cuda_runtime.h>
#include <cstdint>

#define NMAX 50000
#define EMAX 800000
#define H    128
#define G    64

// ---------------- scratch (static device globals; no allocation) ----------------
__device__ float4 g_t4  [(size_t)NMAX * H / 4];
__device__ float4 g_acc4[(size_t)NMAX * H / 4];
__device__ float4 g_h4  [(size_t)NMAX * H / 4];
__device__ float  g_deg [NMAX];
__device__ float  g_dinv[NMAX];
__device__ float  g_pool[G * H];
__device__ float  g_cnt [G];
__device__ int    g_is64;          // 1 if index inputs are int64, 0 if int32

#define g_t   ((float*)g_t4)
#define g_acc ((float*)g_acc4)
#define g_h   ((float*)g_h4)

// Read element `pos` of an index array whose dtype we detected at runtime.
__device__ __forceinline__ int idx_at(const void* p, size_t pos) {
    if (g_is64) return (int)((const long long*)p)[pos];
    return ((const int*)p)[pos];
}

// ---------------- dtype detection (single block) ----------------
// If the buffer holds int32 indices, the int64 view combines two indices:
// value = lo + hi*2^32, with hi almost surely nonzero somewhere in the first
// 4096 entries -> out of [0,N) -> int32 mode.
__global__ void k_detect(const void* ei, long long total_elems, int N) {
    if (threadIdx.x == 0) g_is64 = 1;
    __syncthreads();
    const long long* p = (const long long*)ei;
    long long n = total_elems < 4096 ? total_elems : 4096;
    int bad = 0;
    for (long long i = threadIdx.x; i < n; i += blockDim.x) {
        long long v = p[i];
        if (v < 0 || v >= N) bad = 1;
    }
    if (bad) atomicExch(&g_is64, 0);
}

// ---------------- degree / norm ----------------
__global__ void k_deg_init(int N) {
    int i = blockIdx.x * blockDim.x + threadIdx.x;
    if (i < N) g_deg[i] = 1.0f;   // self-loop
}

__global__ void k_deg_edges(const void* ei, int E, int N) {
    int e = blockIdx.x * blockDim.x + threadIdx.x;
    if (e < E) {
        int d = idx_at(ei, (size_t)E + e);   // dst = second half
        d = min(max(d, 0), N - 1);
        atomicAdd(&g_deg[d], 1.0f);
    }
}

__global__ void k_dinv(int N) {
    int i = blockIdx.x * blockDim.x + threadIdx.x;
    if (i < N) g_dinv[i] = rsqrtf(g_deg[i]);
}

// ---------------- GEMM: t = acc = diag(dinv) * (A @ W)  ----------------
// A: [N, K] row-major, W: [K, 128] row-major. Tile: BM=64, BN=128, BK=16.
template<int K, bool FROM_H>
__global__ void k_gemm(const float* __restrict__ Ain, const float* __restrict__ W, int N) {
    const float* A = FROM_H ? g_h : Ain;
    __shared__ float As[16][64 + 4];
    __shared__ float Bs[16][128];
    const int tid  = threadIdx.x;
    const int row0 = blockIdx.x * 64;
    const int tx   = tid & 15;
    const int ty   = tid >> 4;

    float acc[4][8];
#pragma unroll
    for (int i = 0; i < 4; i++)
#pragma unroll
        for (int j = 0; j < 8; j++) acc[i][j] = 0.0f;

    const int am = tid >> 2;
    const int ak = (tid & 3) * 4;

    for (int k0 = 0; k0 < K; k0 += 16) {
        float4 av = make_float4(0.f, 0.f, 0.f, 0.f);
        if (row0 + am < N)
            av = *(const float4*)(A + (size_t)(row0 + am) * K + k0 + ak);
        As[ak + 0][am] = av.x; As[ak + 1][am] = av.y;
        As[ak + 2][am] = av.z; As[ak + 3][am] = av.w;
#pragma unroll
        for (int r = 0; r < 2; r++) {
            int lin = tid + r * 256;
            int bk  = lin >> 5;
            int bn  = (lin & 31) * 4;
            float4 bv = *(const float4*)(W + (size_t)(k0 + bk) * 128 + bn);
            Bs[bk][bn + 0] = bv.x; Bs[bk][bn + 1] = bv.y;
            Bs[bk][bn + 2] = bv.z; Bs[bk][bn + 3] = bv.w;
        }
        __syncthreads();
#pragma unroll
        for (int k = 0; k < 16; k++) {
            float a[4], b[8];
#pragma unroll
            for (int i = 0; i < 4; i++) a[i] = As[k][ty * 4 + i];
#pragma unroll
            for (int j = 0; j < 8; j++) b[j] = Bs[k][tx * 8 + j];
#pragma unroll
            for (int i = 0; i < 4; i++)
#pragma unroll
                for (int j = 0; j < 8; j++)
                    acc[i][j] = fmaf(a[i], b[j], acc[i][j]);
        }
        __syncthreads();
    }

#pragma unroll
    for (int i = 0; i < 4; i++) {
        int row = row0 + ty * 4 + i;
        if (row >= N) continue;
        float dv = g_dinv[row];
#pragma unroll
        for (int j = 0; j < 8; j += 4) {
            float4 v;
            v.x = acc[i][j + 0] * dv; v.y = acc[i][j + 1] * dv;
            v.z = acc[i][j + 2] * dv; v.w = acc[i][j + 3] * dv;
            size_t idx = ((size_t)row * H + tx * 8 + j) / 4;
            g_t4  [idx] = v;
            g_acc4[idx] = v;   // self-loop contribution = init
        }
    }
}

// ---------------- edge scatter: acc[dst] += t[src] (one warp per edge) -------
__global__ void k_scatter(const void* ei, int E, int N) {
    int warp = (blockIdx.x * blockDim.x + threadIdx.x) >> 5;
    int lane = threadIdx.x & 31;
    if (warp >= E) return;
    int s = idx_at(ei, warp);                 // src = first half
    int d = idx_at(ei, (size_t)E + warp);     // dst = second half
    s = min(max(s, 0), N - 1);
    d = min(max(d, 0), N - 1);
    float4 v = g_t4[(size_t)s * (H / 4) + lane];
    float* a = g_acc + (size_t)d * H + lane * 4;
    atomicAdd(a + 0, v.x);
    atomicAdd(a + 1, v.y);
    atomicAdd(a + 2, v.z);
    atomicAdd(a + 3, v.w);
}

// ---------------- finalize with BN + ReLU: h = relu(bn(dinv*acc + b)) --------
__global__ void k_bn_relu(const float* __restrict__ b,  const float* __restrict__ gg,
                          const float* __restrict__ be, const float* __restrict__ mm,
                          const float* __restrict__ vv, int N) {
    int idx = blockIdx.x * blockDim.x + threadIdx.x;
    if (idx >= N * (H / 4)) return;
    int row = idx >> 5;
    int c   = (idx & 31) * 4;
    float dv = g_dinv[row];
    float4 a  = g_acc4[idx];
    float4 bb = *(const float4*)(b  + c);
    float4 gv = *(const float4*)(gg + c);
    float4 bt = *(const float4*)(be + c);
    float4 mu = *(const float4*)(mm + c);
    float4 va = *(const float4*)(vv + c);
    float4 r;
    r.x = fmaxf((a.x * dv + bb.x - mu.x) * rsqrtf(va.x + 1e-5f) * gv.x + bt.x, 0.f);
    r.y = fmaxf((a.y * dv + bb.y - mu.y) * rsqrtf(va.y + 1e-5f) * gv.y + bt.y, 0.f);
    r.z = fmaxf((a.z * dv + bb.z - mu.z) * rsqrtf(va.z + 1e-5f) * gv.z + bt.z, 0.f);
    r.w = fmaxf((a.w * dv + bb.w - mu.w) * rsqrtf(va.w + 1e-5f) * gv.w + bt.w, 0.f);
    g_h4[idx] = r;
}

// ---------------- finalize layer 3: h = dinv*acc + b (no BN) ----------------
__global__ void k_final3(const float* __restrict__ b, int N) {
    int idx = blockIdx.x * blockDim.x + threadIdx.x;
    if (idx >= N * (H / 4)) return;
    int row = idx >> 5;
    int c   = (idx & 31) * 4;
    float dv = g_dinv[row];
    float4 a  = g_acc4[idx];
    float4 bb = *(const float4*)(b + c);
    float4 r;
    r.x = a.x * dv + bb.x; r.y = a.y * dv + bb.y;
    r.z = a.z * dv + bb.z; r.w = a.w * dv + bb.w;
    g_h4[idx] = r;
}

// ---------------- pooling ----------------
__global__ void k_pool_zero() {
    int i = blockIdx.x * blockDim.x + threadIdx.x;
    if (i < G * H) g_pool[i] = 0.0f;
    if (i < G)     g_cnt[i]  = 0.0f;
}

// batch is sorted: accumulate locally, flush on graph-id change.
__global__ void k_pool(const void* batch, int N) {
    const int col = threadIdx.x;              // 128 threads
    int r0 = blockIdx.x * 256;
    if (r0 >= N) return;
    int r1 = min(r0 + 256, N);
    float sum = 0.0f;
    int   cnt = 0;
    int   cur = idx_at(batch, r0) & (G - 1);
    for (int r = r0; r < r1; r++) {
        int b = idx_at(batch, r) & (G - 1);
        if (b != cur) {
            atomicAdd(&g_pool[cur * H + col], sum);
            if (col == 0) atomicAdd(&g_cnt[cur], (float)cnt);
            sum = 0.0f; cnt = 0; cur = b;
        }
        sum += g_h[(size_t)r * H + col];
        cnt++;
    }
    atomicAdd(&g_pool[cur * H + col], sum);
    if (col == 0) atomicAdd(&g_cnt[cur], (float)cnt);
}

// ---------------- classifier head: one block per graph ----------------
__global__ void k_classifier(const float* __restrict__ Wc1, const float* __restrict__ bc1,
                             const float* __restrict__ Wc2, const float* __restrict__ bc2,
                             float* __restrict__ out) {
    __shared__ float pooled[H];
    __shared__ float z[64];
    const int g = blockIdx.x;
    const int t = threadIdx.x;   // 64 threads
    float cnt = fmaxf(g_cnt[g], 1.0f);
    pooled[t]      = g_pool[g * H + t]      / cnt;
    pooled[t + 64] = g_pool[g * H + t + 64] / cnt;
    __syncthreads();
    float s = bc1[t];
#pragma unroll 4
    for (int h = 0; h < H; h++) s = fmaf(pooled[h], Wc1[h * 64 + t], s);
    z[t] = fmaxf(s, 0.0f);
    __syncthreads();
    if (t < 16) {
        float o = bc2[t];
#pragma unroll 4
        for (int k = 0; k < 64; k++) o = fmaf(z[k], Wc2[k * 16 + t], o);
        out[g * 16 + t] = o;
    }
}

// ---------------- launch ----------------
extern "C" void kernel_launch(void* const* d_in, const int* in_sizes, int n_in,
                              void* d_out, int out_size) {
    const float* x     = (const float*)d_in[0];
    const void*  ei    = d_in[1];
    const void*  batch = d_in[2];
    const float* W1 = (const float*)d_in[3],  *b1 = (const float*)d_in[4];
    const float* W2 = (const float*)d_in[5],  *b2 = (const float*)d_in[6];
    const float* W3 = (const float*)d_in[7],  *b3 = (const float*)d_in[8];
    const float* bn1_g = (const float*)d_in[9],  *bn1_b = (const float*)d_in[10];
    const float* bn1_m = (const float*)d_in[11], *bn1_v = (const float*)d_in[12];
    const float* bn2_g = (const float*)d_in[13], *bn2_b = (const float*)d_in[14];
    const float* bn2_m = (const float*)d_in[15], *bn2_v = (const float*)d_in[16];
    const float* Wc1 = (const float*)d_in[17], *bc1 = (const float*)d_in[18];
    const float* Wc2 = (const float*)d_in[19], *bc2 = (const float*)d_in[20];
    float* out = (float*)d_out;

    const int N = in_sizes[0] / 256;
    const int E = in_sizes[1] / 2;

    const int nThr = 256;
    const int nBlkN     = (N + nThr - 1) / nThr;
    const int nBlkE     = (E + nThr - 1) / nThr;
    const int gemmBlk   = (N + 63) / 64;
    const int scatBlk   = (E + 7) / 8;                 // 8 warps / block
    const int finBlk    = (N * (H / 4) + nThr - 1) / nThr;
    const int poolBlk   = (N + 255) / 256;

    // dtype detection: if int32, the int64 view (half the element count) has
    // out-of-range values with overwhelming probability.
    k_detect<<<1, 256>>>(ei, (long long)E, N);   // inspect first min(E,4096) int64 views

    // normalization
    k_deg_init <<<nBlkN, nThr>>>(N);
    k_deg_edges<<<nBlkE, nThr>>>(ei, E, N);
    k_dinv     <<<nBlkN, nThr>>>(N);

    // layer 1
    k_gemm<256, false><<<gemmBlk, nThr>>>(x, W1, N);
    k_scatter  <<<scatBlk, nThr>>>(ei, E, N);
    k_bn_relu  <<<finBlk, nThr>>>(b1, bn1_g, bn1_b, bn1_m, bn1_v, N);

    // layer 2
    k_gemm<128, true><<<gemmBlk, nThr>>>(nullptr, W2, N);
    k_scatter  <<<scatBlk, nThr>>>(ei, E, N);
    k_bn_relu  <<<finBlk, nThr>>>(b2, bn2_g, bn2_b, bn2_m, bn2_v, N);

    // layer 3
    k_gemm<128, true><<<gemmBlk, nThr>>>(nullptr, W3, N);
    k_scatter  <<<scatBlk, nThr>>>(ei, E, N);
    k_final3   <<<finBlk, nThr>>>(b3, N);

    // pooling + head
    k_pool_zero<<<(G * H + nThr - 1) / nThr, nThr>>>();
    k_pool     <<<poolBlk, 128>>>(batch, N);
    k_classifier<<<G, 64>>>(Wc1, bc1, Wc2, bc2, out);
}

// round 14
// speedup vs baseline: 1.8365x; 1.8365x over previous
#include <cuda_runtime.h>
#include <cstdint>

#define NMAX 50000
#define EMAX 800000
#define H    128
#define G    64

// ---------------- scratch (static device globals; no allocation) ----------------
__device__ float4 g_t4  [(size_t)NMAX * H / 4];   // dinv-scaled GEMM output
__device__ float4 g_h4  [(size_t)NMAX * H / 4];   // layer activation
__device__ float  g_dinv[NMAX];
__device__ int    g_cnti[NMAX];                   // in-degree (no self-loop)
__device__ int    g_offs[NMAX + 1];               // CSR offsets
__device__ int    g_cur [NMAX];                   // placement cursors
__device__ int    g_csr [EMAX];                   // CSR src lists (grouped by dst)
__device__ float  g_pool[G * H];
__device__ float  g_cnt [G];
__device__ int    g_is64;                         // index dtype flag

#define g_h ((float*)g_h4)

__device__ __forceinline__ int idx_at(const void* p, size_t pos) {
    if (g_is64) return (int)((const long long*)p)[pos];
    return ((const int*)p)[pos];
}

// ---------------- dtype detection (single block) ----------------
__global__ void k_detect(const void* ei, long long total_elems, int N) {
    if (threadIdx.x == 0) g_is64 = 1;
    __syncthreads();
    const long long* p = (const long long*)ei;
    long long n = total_elems < 4096 ? total_elems : 4096;
    int bad = 0;
    for (long long i = threadIdx.x; i < n; i += blockDim.x) {
        long long v = p[i];
        if (v < 0 || v >= N) bad = 1;
    }
    if (bad) atomicExch(&g_is64, 0);
}

// ---------------- CSR build ----------------
__global__ void k_zero_cnt(int N) {
    int i = blockIdx.x * blockDim.x + threadIdx.x;
    if (i < N) g_cnti[i] = 0;
}

__global__ void k_hist(const void* ei, int E, int N) {
    int e = blockIdx.x * blockDim.x + threadIdx.x;
    if (e < E) {
        int d = idx_at(ei, (size_t)E + e);
        d = min(max(d, 0), N - 1);
        atomicAdd(&g_cnti[d], 1);
    }
}

// single-block exclusive scan of g_cnti -> g_offs; also zero cursors, compute dinv
__global__ void k_scan(int N) {
    __shared__ int warpsums[32];
    const int T = 1024;
    int tid  = threadIdx.x;
    int lane = tid & 31, wid = tid >> 5;
    int chunk = (N + T - 1) / T;
    int lo = tid * chunk, hi = min(lo + chunk, N);
    int s = 0;
    for (int i = lo; i < hi; i++) s += g_cnti[i];
    int v = s;
#pragma unroll
    for (int o = 1; o < 32; o <<= 1) {
        int u = __shfl_up_sync(0xFFFFFFFF, v, o);
        if (lane >= o) v += u;
    }
    if (lane == 31) warpsums[wid] = v;
    __syncthreads();
    if (wid == 0) {
        int w = warpsums[lane];
#pragma unroll
        for (int o = 1; o < 32; o <<= 1) {
            int u = __shfl_up_sync(0xFFFFFFFF, w, o);
            if (lane >= o) w += u;
        }
        warpsums[lane] = w;
    }
    __syncthreads();
    int base = (wid > 0 ? warpsums[wid - 1] : 0) + (v - s);  // exclusive prefix
    int run = base;
    for (int i = lo; i < hi; i++) {
        g_offs[i] = run;
        g_cur [i] = 0;
        g_dinv[i] = rsqrtf(1.0f + (float)g_cnti[i]);  // +1 self-loop
        run += g_cnti[i];
    }
    if (hi == N && lo < N) g_offs[N] = run;
    if (N <= lo && tid == T - 1) g_offs[N] = 0;  // degenerate safety
}

__global__ void k_fill(const void* ei, int E, int N) {
    int e = blockIdx.x * blockDim.x + threadIdx.x;
    if (e >= E) return;
    int s = idx_at(ei, e);
    int d = idx_at(ei, (size_t)E + e);
    s = min(max(s, 0), N - 1);
    d = min(max(d, 0), N - 1);
    int pos = g_offs[d] + atomicAdd(&g_cur[d], 1);
    g_csr[pos] = s;
}

// ---------------- GEMM: t = diag(dinv) * (A @ W) ----------------
// A: [N, K] row-major, W: [K, 128]. Tile BM=64, BN=128, BK=16; 256 thr, 4x8 micro.
template<int K, bool FROM_H>
__global__ void k_gemm(const float* __restrict__ Ain, const float* __restrict__ W, int N) {
    const float* A = FROM_H ? g_h : Ain;
    __shared__ float As[16][64 + 4];
    __shared__ float Bs[16][128];
    const int tid  = threadIdx.x;
    const int row0 = blockIdx.x * 64;
    const int tx   = tid & 15;
    const int ty   = tid >> 4;

    float acc[4][8];
#pragma unroll
    for (int i = 0; i < 4; i++)
#pragma unroll
        for (int j = 0; j < 8; j++) acc[i][j] = 0.0f;

    const int am = tid >> 2;
    const int ak = (tid & 3) * 4;

    for (int k0 = 0; k0 < K; k0 += 16) {
        float4 av = make_float4(0.f, 0.f, 0.f, 0.f);
        if (row0 + am < N)
            av = *(const float4*)(A + (size_t)(row0 + am) * K + k0 + ak);
        As[ak + 0][am] = av.x; As[ak + 1][am] = av.y;
        As[ak + 2][am] = av.z; As[ak + 3][am] = av.w;
#pragma unroll
        for (int r = 0; r < 2; r++) {
            int lin = tid + r * 256;
            int bk  = lin >> 5;
            int bn  = (lin & 31) * 4;
            float4 bv = *(const float4*)(W + (size_t)(k0 + bk) * 128 + bn);
            Bs[bk][bn + 0] = bv.x; Bs[bk][bn + 1] = bv.y;
            Bs[bk][bn + 2] = bv.z; Bs[bk][bn + 3] = bv.w;
        }
        __syncthreads();
#pragma unroll
        for (int k = 0; k < 16; k++) {
            float a[4], b[8];
#pragma unroll
            for (int i = 0; i < 4; i++) a[i] = As[k][ty * 4 + i];
#pragma unroll
            for (int j = 0; j < 8; j++) b[j] = Bs[k][tx * 8 + j];
#pragma unroll
            for (int i = 0; i < 4; i++)
#pragma unroll
                for (int j = 0; j < 8; j++)
                    acc[i][j] = fmaf(a[i], b[j], acc[i][j]);
        }
        __syncthreads();
    }

#pragma unroll
    for (int i = 0; i < 4; i++) {
        int row = row0 + ty * 4 + i;
        if (row >= N) continue;
        float dv = g_dinv[row];
#pragma unroll
        for (int j = 0; j < 8; j += 4) {
            float4 v;
            v.x = acc[i][j + 0] * dv; v.y = acc[i][j + 1] * dv;
            v.z = acc[i][j + 2] * dv; v.w = acc[i][j + 3] * dv;
            g_t4[((size_t)row * H + tx * 8 + j) / 4] = v;
        }
    }
}

// ---------------- gather + epilogue (warp per node) ----------------
// acc = t[node] + sum_{s in CSR[node]} t[s];  out = epilogue(acc * dinv[node])
#define F4ADD(a, b) { a.x += b.x; a.y += b.y; a.z += b.z; a.w += b.w; }

template<bool BN>
__global__ void k_gather(const float* __restrict__ b,  const float* __restrict__ gg,
                         const float* __restrict__ be, const float* __restrict__ mm,
                         const float* __restrict__ vv, int N) {
    int node = (blockIdx.x * blockDim.x + threadIdx.x) >> 5;
    int lane = threadIdx.x & 31;
    if (node >= N) return;
    const int beg = g_offs[node];
    const int end = g_offs[node + 1];

    float4 a0 = g_t4[(size_t)node * 32 + lane];   // self-loop
    float4 a1 = make_float4(0.f, 0.f, 0.f, 0.f);
    float4 a2 = make_float4(0.f, 0.f, 0.f, 0.f);
    float4 a3 = make_float4(0.f, 0.f, 0.f, 0.f);

    int j = beg;
    for (; j + 4 <= end; j += 4) {
        int n0 = g_csr[j + 0], n1 = g_csr[j + 1];
        int n2 = g_csr[j + 2], n3 = g_csr[j + 3];
        float4 v0 = g_t4[(size_t)n0 * 32 + lane];
        float4 v1 = g_t4[(size_t)n1 * 32 + lane];
        float4 v2 = g_t4[(size_t)n2 * 32 + lane];
        float4 v3 = g_t4[(size_t)n3 * 32 + lane];
        F4ADD(a0, v0); F4ADD(a1, v1); F4ADD(a2, v2); F4ADD(a3, v3);
    }
    for (; j < end; j++) {
        float4 v = g_t4[(size_t)g_csr[j] * 32 + lane];
        F4ADD(a0, v);
    }
    F4ADD(a0, a1); F4ADD(a2, a3); F4ADD(a0, a2);

    const float dv = g_dinv[node];
    const int c = lane * 4;
    float4 bb = *(const float4*)(b + c);
    float4 r;
    if (BN) {
        float4 gv = *(const float4*)(gg + c);
        float4 bt = *(const float4*)(be + c);
        float4 mu = *(const float4*)(mm + c);
        float4 va = *(const float4*)(vv + c);
        r.x = fmaxf((a0.x * dv + bb.x - mu.x) * rsqrtf(va.x + 1e-5f) * gv.x + bt.x, 0.f);
        r.y = fmaxf((a0.y * dv + bb.y - mu.y) * rsqrtf(va.y + 1e-5f) * gv.y + bt.y, 0.f);
        r.z = fmaxf((a0.z * dv + bb.z - mu.z) * rsqrtf(va.z + 1e-5f) * gv.z + bt.z, 0.f);
        r.w = fmaxf((a0.w * dv + bb.w - mu.w) * rsqrtf(va.w + 1e-5f) * gv.w + bt.w, 0.f);
    } else {
        r.x = a0.x * dv + bb.x; r.y = a0.y * dv + bb.y;
        r.z = a0.z * dv + bb.z; r.w = a0.w * dv + bb.w;
    }
    g_h4[(size_t)node * 32 + lane] = r;
}

// ---------------- pooling ----------------
__global__ void k_pool_zero() {
    int i = blockIdx.x * blockDim.x + threadIdx.x;
    if (i < G * H) g_pool[i] = 0.0f;
    if (i < G)     g_cnt[i]  = 0.0f;
}

__global__ void k_pool(const void* batch, int N) {
    const int col = threadIdx.x;              // 128 threads
    int r0 = blockIdx.x * 256;
    if (r0 >= N) return;
    int r1 = min(r0 + 256, N);
    float sum = 0.0f;
    int   cnt = 0;
    int   cur = idx_at(batch, r0) & (G - 1);
    for (int r = r0; r < r1; r++) {
        int b = idx_at(batch, r) & (G - 1);
        if (b != cur) {
            atomicAdd(&g_pool[cur * H + col], sum);
            if (col == 0) atomicAdd(&g_cnt[cur], (float)cnt);
            sum = 0.0f; cnt = 0; cur = b;
        }
        sum += g_h[(size_t)r * H + col];
        cnt++;
    }
    atomicAdd(&g_pool[cur * H + col], sum);
    if (col == 0) atomicAdd(&g_cnt[cur], (float)cnt);
}

// ---------------- classifier head ----------------
__global__ void k_classifier(const float* __restrict__ Wc1, const float* __restrict__ bc1,
                             const float* __restrict__ Wc2, const float* __restrict__ bc2,
                             float* __restrict__ out) {
    __shared__ float pooled[H];
    __shared__ float z[64];
    const int g = blockIdx.x;
    const int t = threadIdx.x;   // 64 threads
    float cnt = fmaxf(g_cnt[g], 1.0f);
    pooled[t]      = g_pool[g * H + t]      / cnt;
    pooled[t + 64] = g_pool[g * H + t + 64] / cnt;
    __syncthreads();
    float s = bc1[t];
#pragma unroll 4
    for (int h = 0; h < H; h++) s = fmaf(pooled[h], Wc1[h * 64 + t], s);
    z[t] = fmaxf(s, 0.0f);
    __syncthreads();
    if (t < 16) {
        float o = bc2[t];
#pragma unroll 4
        for (int k = 0; k < 64; k++) o = fmaf(z[k], Wc2[k * 16 + t], o);
        out[g * 16 + t] = o;
    }
}

// ---------------- launch ----------------
extern "C" void kernel_launch(void* const* d_in, const int* in_sizes, int n_in,
                              void* d_out, int out_size) {
    const float* x     = (const float*)d_in[0];
    const void*  ei    = d_in[1];
    const void*  batch = d_in[2];
    const float* W1 = (const float*)d_in[3],  *b1 = (const float*)d_in[4];
    const float* W2 = (const float*)d_in[5],  *b2 = (const float*)d_in[6];
    const float* W3 = (const float*)d_in[7],  *b3 = (const float*)d_in[8];
    const float* bn1_g = (const float*)d_in[9],  *bn1_b = (const float*)d_in[10];
    const float* bn1_m = (const float*)d_in[11], *bn1_v = (const float*)d_in[12];
    const float* bn2_g = (const float*)d_in[13], *bn2_b = (const float*)d_in[14];
    const float* bn2_m = (const float*)d_in[15], *bn2_v = (const float*)d_in[16];
    const float* Wc1 = (const float*)d_in[17], *bc1 = (const float*)d_in[18];
    const float* Wc2 = (const float*)d_in[19], *bc2 = (const float*)d_in[20];
    float* out = (float*)d_out;

    const int N = in_sizes[0] / 256;
    const int E = in_sizes[1] / 2;

    const int nThr = 256;
    const int nBlkN   = (N + nThr - 1) / nThr;
    const int nBlkE   = (E + nThr - 1) / nThr;
    const int gemmBlk = (N + 63) / 64;
    const int gathBlk = (N * 32 + nThr - 1) / nThr;    // warp per node
    const int poolBlk = (N + 255) / 256;

    // dtype detection + CSR build
    k_detect  <<<1, 256>>>(ei, (long long)E, N);
    k_zero_cnt<<<nBlkN, nThr>>>(N);
    k_hist    <<<nBlkE, nThr>>>(ei, E, N);
    k_scan    <<<1, 1024>>>(N);
    k_fill    <<<nBlkE, nThr>>>(ei, E, N);

    // layer 1
    k_gemm<256, false><<<gemmBlk, nThr>>>(x, W1, N);
    k_gather<true>    <<<gathBlk, nThr>>>(b1, bn1_g, bn1_b, bn1_m, bn1_v, N);

    // layer 2
    k_gemm<128, true> <<<gemmBlk, nThr>>>(nullptr, W2, N);
    k_gather<true>    <<<gathBlk, nThr>>>(b2, bn2_g, bn2_b, bn2_m, bn2_v, N);

    // layer 3
    k_gemm<128, true> <<<gemmBlk, nThr>>>(nullptr, W3, N);
    k_gather<false>   <<<gathBlk, nThr>>>(b3, nullptr, nullptr, nullptr, nullptr, N);

    // pooling + head
    k_pool_zero<<<(G * H + nThr - 1) / nThr, nThr>>>();
    k_pool     <<<poolBlk, 128>>>(batch, N);
    k_classifier<<<G, 64>>>(Wc1, bc1, Wc2, bc2, out);
}

// round 16
// speedup vs baseline: 2.2034x; 1.1998x over previous
#include <cuda_runtime.h>
#include <cstdint>

#define NMAX 50000
#define EMAX 800000
#define H    128
#define G    64
#define SCAN_B 256   // blocks in parallel scan

// ---------------- scratch (static device globals; no allocation) ----------------
__device__ float4 g_t4  [(size_t)NMAX * H / 4];   // dinv-scaled GEMM output
__device__ float4 g_h4  [(size_t)NMAX * H / 4];   // layer activation
__device__ float  g_dinv[NMAX];
__device__ int    g_cnti[NMAX];                   // in-degree (no self-loop)
__device__ int    g_offs[NMAX + 1];               // CSR offsets
__device__ int    g_cur [NMAX];                   // placement cursors
__device__ int    g_csr [EMAX];                   // CSR src lists (grouped by dst)
__device__ int    g_bsum[SCAN_B];                 // per-block sums for scan
__device__ float  g_pool[G * H];
__device__ float  g_cnt [G];
__device__ int    g_is64;                         // index dtype flag

#define g_h ((float*)g_h4)

__device__ __forceinline__ int idx_at(const void* p, size_t pos) {
    if (g_is64) return (int)((const long long*)p)[pos];
    return ((const int*)p)[pos];
}

// ---------------- dtype detection (single block) ----------------
__global__ void k_detect(const void* ei, long long total_elems, int N) {
    if (threadIdx.x == 0) g_is64 = 1;
    __syncthreads();
    const long long* p = (const long long*)ei;
    long long n = total_elems < 4096 ? total_elems : 4096;
    int bad = 0;
    for (long long i = threadIdx.x; i < n; i += blockDim.x) {
        long long v = p[i];
        if (v < 0 || v >= N) bad = 1;
    }
    if (bad) atomicExch(&g_is64, 0);
}

// ---------------- CSR build ----------------
__global__ void k_zero_cnt(int N) {
    int i = blockIdx.x * blockDim.x + threadIdx.x;
    if (i < N) g_cnti[i] = 0;
}

__global__ void k_hist(const void* ei, int E, int N) {
    int e = blockIdx.x * blockDim.x + threadIdx.x;
    if (e < E) {
        int d = idx_at(ei, (size_t)E + e);
        d = min(max(d, 0), N - 1);
        atomicAdd(&g_cnti[d], 1);
    }
}

// ---- parallel scan: phase 1 — per-block chunk sums ----
__global__ void k_scan1(int N) {
    __shared__ int ws[8];
    const int chunk = (N + SCAN_B - 1) / SCAN_B;     // <= 256
    const int lo = blockIdx.x * chunk;
    const int t = threadIdx.x, lane = t & 31, wid = t >> 5;
    int i = lo + t;
    int v = (t < chunk && i < N) ? g_cnti[i] : 0;
    int x = v;
#pragma unroll
    for (int o = 1; o < 32; o <<= 1) {
        int u = __shfl_up_sync(0xFFFFFFFF, x, o);
        if (lane >= o) x += u;
    }
    if (lane == 31) ws[wid] = x;
    __syncthreads();
    if (t == 0) {
        int s = 0;
#pragma unroll
        for (int w = 0; w < 8; w++) s += ws[w];
        g_bsum[blockIdx.x] = s;
    }
}

// ---- phase 2 — exclusive scan of the 256 block sums (one block) ----
__global__ void k_scan2(int N) {
    __shared__ int ws[8];
    const int t = threadIdx.x, lane = t & 31, wid = t >> 5;
    int v = g_bsum[t];
    int x = v;
#pragma unroll
    for (int o = 1; o < 32; o <<= 1) {
        int u = __shfl_up_sync(0xFFFFFFFF, x, o);
        if (lane >= o) x += u;
    }
    if (lane == 31) ws[wid] = x;
    __syncthreads();
    if (wid == 0 && lane < 8) {
        int w = ws[lane];
#pragma unroll
        for (int o = 1; o < 8; o <<= 1) {
            int u = __shfl_up_sync(0xFF, w, o);
            if (lane >= o) w += u;
        }
        ws[lane] = w;
    }
    __syncthreads();
    int excl = x - v + (wid ? ws[wid - 1] : 0);
    g_bsum[t] = excl;
    if (t == SCAN_B - 1) g_offs[N] = excl + v;   // total edge count
}

// ---- phase 3 — block-wide exclusive scan of each chunk + base; offs/cur/dinv ----
__global__ void k_scan3(int N) {
    __shared__ int ws[8];
    const int chunk = (N + SCAN_B - 1) / SCAN_B;
    const int lo = blockIdx.x * chunk;
    const int t = threadIdx.x, lane = t & 31, wid = t >> 5;
    int i = lo + t;
    bool act = (t < chunk && i < N);
    int v = act ? g_cnti[i] : 0;
    int x = v;
#pragma unroll
    for (int o = 1; o < 32; o <<= 1) {
        int u = __shfl_up_sync(0xFFFFFFFF, x, o);
        if (lane >= o) x += u;
    }
    if (lane == 31) ws[wid] = x;
    __syncthreads();
    if (wid == 0 && lane < 8) {
        int w = ws[lane];
#pragma unroll
        for (int o = 1; o < 8; o <<= 1) {
            int u = __shfl_up_sync(0xFF, w, o);
            if (lane >= o) w += u;
        }
        ws[lane] = w;
    }
    __syncthreads();
    if (act) {
        int excl = x - v + (wid ? ws[wid - 1] : 0) + g_bsum[blockIdx.x];
        g_offs[i] = excl;
        g_cur [i] = 0;
        g_dinv[i] = rsqrtf(1.0f + (float)v);   // +1 self-loop
    }
}

__global__ void k_fill(const void* ei, int E, int N) {
    int e = blockIdx.x * blockDim.x + threadIdx.x;
    if (e >= E) return;
    int s = idx_at(ei, e);
    int d = idx_at(ei, (size_t)E + e);
    s = min(max(s, 0), N - 1);
    d = min(max(d, 0), N - 1);
    int pos = g_offs[d] + atomicAdd(&g_cur[d], 1);
    g_csr[pos] = s;
}

// ---------------- GEMM: t = diag(dinv) * (A @ W) ----------------
// A: [N, K] row-major, W: [K, 128]. Tile BM=64, BN=128, BK=16; 256 thr, 4x8 micro.
template<int K, bool FROM_H>
__global__ void k_gemm(const float* __restrict__ Ain, const float* __restrict__ W, int N) {
    const float* A = FROM_H ? g_h : Ain;
    __shared__ float As[16][64 + 4];
    __shared__ float Bs[16][128];
    const int tid  = threadIdx.x;
    const int row0 = blockIdx.x * 64;
    const int tx   = tid & 15;
    const int ty   = tid >> 4;

    float acc[4][8];
#pragma unroll
    for (int i = 0; i < 4; i++)
#pragma unroll
        for (int j = 0; j < 8; j++) acc[i][j] = 0.0f;

    const int am = tid >> 2;
    const int ak = (tid & 3) * 4;

    for (int k0 = 0; k0 < K; k0 += 16) {
        float4 av = make_float4(0.f, 0.f, 0.f, 0.f);
        if (row0 + am < N)
            av = *(const float4*)(A + (size_t)(row0 + am) * K + k0 + ak);
        As[ak + 0][am] = av.x; As[ak + 1][am] = av.y;
        As[ak + 2][am] = av.z; As[ak + 3][am] = av.w;
#pragma unroll
        for (int r = 0; r < 2; r++) {
            int lin = tid + r * 256;
            int bk  = lin >> 5;
            int bn  = (lin & 31) * 4;
            float4 bv = *(const float4*)(W + (size_t)(k0 + bk) * 128 + bn);
            Bs[bk][bn + 0] = bv.x; Bs[bk][bn + 1] = bv.y;
            Bs[bk][bn + 2] = bv.z; Bs[bk][bn + 3] = bv.w;
        }
        __syncthreads();
#pragma unroll
        for (int k = 0; k < 16; k++) {
            float a[4], b[8];
#pragma unroll
            for (int i = 0; i < 4; i++) a[i] = As[k][ty * 4 + i];
#pragma unroll
            for (int j = 0; j < 8; j++) b[j] = Bs[k][tx * 8 + j];
#pragma unroll
            for (int i = 0; i < 4; i++)
#pragma unroll
                for (int j = 0; j < 8; j++)
                    acc[i][j] = fmaf(a[i], b[j], acc[i][j]);
        }
        __syncthreads();
    }

#pragma unroll
    for (int i = 0; i < 4; i++) {
        int row = row0 + ty * 4 + i;
        if (row >= N) continue;
        float dv = g_dinv[row];
#pragma unroll
        for (int j = 0; j < 8; j += 4) {
            float4 v;
            v.x = acc[i][j + 0] * dv; v.y = acc[i][j + 1] * dv;
            v.z = acc[i][j + 2] * dv; v.w = acc[i][j + 3] * dv;
            g_t4[((size_t)row * H + tx * 8 + j) / 4] = v;
        }
    }
}

// ---------------- gather + epilogue (warp per node) ----------------
#define F4ADD(a, b) { a.x += b.x; a.y += b.y; a.z += b.z; a.w += b.w; }

template<bool BN>
__global__ void k_gather(const float* __restrict__ b,  const float* __restrict__ gg,
                         const float* __restrict__ be, const float* __restrict__ mm,
                         const float* __restrict__ vv, int N) {
    int node = (blockIdx.x * blockDim.x + threadIdx.x) >> 5;
    int lane = threadIdx.x & 31;
    if (node >= N) return;
    const int beg = g_offs[node];
    const int end = g_offs[node + 1];

    float4 a0 = g_t4[(size_t)node * 32 + lane];   // self-loop
    float4 a1 = make_float4(0.f, 0.f, 0.f, 0.f);
    float4 a2 = make_float4(0.f, 0.f, 0.f, 0.f);
    float4 a3 = make_float4(0.f, 0.f, 0.f, 0.f);

    int j = beg;
    for (; j + 4 <= end; j += 4) {
        int n0 = g_csr[j + 0], n1 = g_csr[j + 1];
        int n2 = g_csr[j + 2], n3 = g_csr[j + 3];
        float4 v0 = g_t4[(size_t)n0 * 32 + lane];
        float4 v1 = g_t4[(size_t)n1 * 32 + lane];
        float4 v2 = g_t4[(size_t)n2 * 32 + lane];
        float4 v3 = g_t4[(size_t)n3 * 32 + lane];
        F4ADD(a0, v0); F4ADD(a1, v1); F4ADD(a2, v2); F4ADD(a3, v3);
    }
    for (; j < end; j++) {
        float4 v = g_t4[(size_t)g_csr[j] * 32 + lane];
        F4ADD(a0, v);
    }
    F4ADD(a0, a1); F4ADD(a2, a3); F4ADD(a0, a2);

    const float dv = g_dinv[node];
    const int c = lane * 4;
    float4 bb = *(const float4*)(b + c);
    float4 r;
    if (BN) {
        float4 gv = *(const float4*)(gg + c);
        float4 bt = *(const float4*)(be + c);
        float4 mu = *(const float4*)(mm + c);
        float4 va = *(const float4*)(vv + c);
        r.x = fmaxf((a0.x * dv + bb.x - mu.x) * rsqrtf(va.x + 1e-5f) * gv.x + bt.x, 0.f);
        r.y = fmaxf((a0.y * dv + bb.y - mu.y) * rsqrtf(va.y + 1e-5f) * gv.y + bt.y, 0.f);
        r.z = fmaxf((a0.z * dv + bb.z - mu.z) * rsqrtf(va.z + 1e-5f) * gv.z + bt.z, 0.f);
        r.w = fmaxf((a0.w * dv + bb.w - mu.w) * rsqrtf(va.w + 1e-5f) * gv.w + bt.w, 0.f);
    } else {
        r.x = a0.x * dv + bb.x; r.y = a0.y * dv + bb.y;
        r.z = a0.z * dv + bb.z; r.w = a0.w * dv + bb.w;
    }
    g_h4[(size_t)node * 32 + lane] = r;
}

// ---------------- pooling ----------------
__global__ void k_pool_zero() {
    int i = blockIdx.x * blockDim.x + threadIdx.x;
    if (i < G * H) g_pool[i] = 0.0f;
    if (i < G)     g_cnt[i]  = 0.0f;
}

__global__ void k_pool(const void* batch, int N) {
    const int col = threadIdx.x;              // 128 threads
    int r0 = blockIdx.x * 256;
    if (r0 >= N) return;
    int r1 = min(r0 + 256, N);
    float sum = 0.0f;
    int   cnt = 0;
    int   cur = idx_at(batch, r0) & (G - 1);
    for (int r = r0; r < r1; r++) {
        int b = idx_at(batch, r) & (G - 1);
        if (b != cur) {
            atomicAdd(&g_pool[cur * H + col], sum);
            if (col == 0) atomicAdd(&g_cnt[cur], (float)cnt);
            sum = 0.0f; cnt = 0; cur = b;
        }
        sum += g_h[(size_t)r * H + col];
        cnt++;
    }
    atomicAdd(&g_pool[cur * H + col], sum);
    if (col == 0) atomicAdd(&g_cnt[cur], (float)cnt);
}

// ---------------- classifier head ----------------
__global__ void k_classifier(const float* __restrict__ Wc1, const float* __restrict__ bc1,
                             const float* __restrict__ Wc2, const float* __restrict__ bc2,
                             float* __restrict__ out) {
    __shared__ float pooled[H];
    __shared__ float z[64];
    const int g = blockIdx.x;
    const int t = threadIdx.x;   // 64 threads
    float cnt = fmaxf(g_cnt[g], 1.0f);
    pooled[t]      = g_pool[g * H + t]      / cnt;
    pooled[t + 64] = g_pool[g * H + t + 64] / cnt;
    __syncthreads();
    float s = bc1[t];
#pragma unroll 4
    for (int h = 0; h < H; h++) s = fmaf(pooled[h], Wc1[h * 64 + t], s);
    z[t] = fmaxf(s, 0.0f);
    __syncthreads();
    if (t < 16) {
        float o = bc2[t];
#pragma unroll 4
        for (int k = 0; k < 64; k++) o = fmaf(z[k], Wc2[k * 16 + t], o);
        out[g * 16 + t] = o;
    }
}

// ---------------- launch ----------------
extern "C" void kernel_launch(void* const* d_in, const int* in_sizes, int n_in,
                              void* d_out, int out_size) {
    const float* x     = (const float*)d_in[0];
    const void*  ei    = d_in[1];
    const void*  batch = d_in[2];
    const float* W1 = (const float*)d_in[3],  *b1 = (const float*)d_in[4];
    const float* W2 = (const float*)d_in[5],  *b2 = (const float*)d_in[6];
    const float* W3 = (const float*)d_in[7],  *b3 = (const float*)d_in[8];
    const float* bn1_g = (const float*)d_in[9],  *bn1_b = (const float*)d_in[10];
    const float* bn1_m = (const float*)d_in[11], *bn1_v = (const float*)d_in[12];
    const float* bn2_g = (const float*)d_in[13], *bn2_b = (const float*)d_in[14];
    const float* bn2_m = (const float*)d_in[15], *bn2_v = (const float*)d_in[16];
    const float* Wc1 = (const float*)d_in[17], *bc1 = (const float*)d_in[18];
    const float* Wc2 = (const float*)d_in[19], *bc2 = (const float*)d_in[20];
    float* out = (float*)d_out;

    const int N = in_sizes[0] / 256;
    const int E = in_sizes[1] / 2;

    const int nThr = 256;
    const int nBlkN   = (N + nThr - 1) / nThr;
    const int nBlkE   = (E + nThr - 1) / nThr;
    const int gemmBlk = (N + 63) / 64;
    const int gathBlk = (N * 32 + nThr - 1) / nThr;    // warp per node
    const int poolBlk = (N + 255) / 256;

    // dtype detection + CSR build (parallel scan)
    k_detect  <<<1, 256>>>(ei, (long long)E, N);
    k_zero_cnt<<<nBlkN, nThr>>>(N);
    k_hist    <<<nBlkE, nThr>>>(ei, E, N);
    k_scan1   <<<SCAN_B, 256>>>(N);
    k_scan2   <<<1, SCAN_B>>>(N);
    k_scan3   <<<SCAN_B, 256>>>(N);
    k_fill    <<<nBlkE, nThr>>>(ei, E, N);

    // layer 1
    k_gemm<256, false><<<gemmBlk, nThr>>>(x, W1, N);
    k_gather<true>    <<<gathBlk, nThr>>>(b1, bn1_g, bn1_b, bn1_m, bn1_v, N);

    // layer 2
    k_gemm<128, true> <<<gemmBlk, nThr>>>(nullptr, W2, N);
    k_gather<true>    <<<gathBlk, nThr>>>(b2, bn2_g, bn2_b, bn2_m, bn2_v, N);

    // layer 3
    k_gemm<128, true> <<<gemmBlk, nThr>>>(nullptr, W3, N);
    k_gather<false>   <<<gathBlk, nThr>>>(b3, nullptr, nullptr, nullptr, nullptr, N);

    // pooling + head
    k_pool_zero<<<(G * H + nThr - 1) / nThr, nThr>>>();
    k_pool     <<<poolBlk, 128>>>(batch, N);
    k_classifier<<<G, 64>>>(Wc1, bc1, Wc2, bc2, out);
}